// round 5
// baseline (speedup 1.0000x reference)
#include <cuda_runtime.h>
#include <cuda_bf16.h>
#include <math.h>
#include <stdint.h>

// ---------------- problem constants ----------------
#define T_SEQ   2048
#define D_MODEL 3072
#define N_HEADS 16
#define K_HEADS 8
#define HDIM    256
#define WINDOW  1024
#define SOFT_CAP 50.0f
#define EPS 1e-6f

// ---------------- scratch (static device globals) ----------------
__device__ float g_q  [(size_t)T_SEQ * N_HEADS * HDIM];
__device__ float g_kv [(size_t)T_SEQ * 16 * HDIM];
__device__ __nv_bfloat16 g_xh [(size_t)T_SEQ * D_MODEL];
__device__ __nv_bfloat16 g_xl [(size_t)T_SEQ * D_MODEL];
__device__ __nv_bfloat16 g_qh [(size_t)T_SEQ * N_HEADS * HDIM];
__device__ __nv_bfloat16 g_ql [(size_t)T_SEQ * N_HEADS * HDIM];
__device__ __nv_bfloat16 g_kvh[(size_t)T_SEQ * 16 * HDIM];
__device__ __nv_bfloat16 g_kvl[(size_t)T_SEQ * 16 * HDIM];
__device__ __nv_bfloat16 g_wqh [(size_t)N_HEADS * HDIM * D_MODEL];
__device__ __nv_bfloat16 g_wql [(size_t)N_HEADS * HDIM * D_MODEL];
__device__ __nv_bfloat16 g_wkvh[(size_t)16 * HDIM * D_MODEL];
__device__ __nv_bfloat16 g_wkvl[(size_t)16 * HDIM * D_MODEL];
__device__ __nv_bfloat16 g_woh [(size_t)D_MODEL * N_HEADS * HDIM];
__device__ __nv_bfloat16 g_wol [(size_t)D_MODEL * N_HEADS * HDIM];
__device__ __nv_bfloat16 g_ench[(size_t)T_SEQ * N_HEADS * HDIM];
__device__ __nv_bfloat16 g_encl[(size_t)T_SEQ * N_HEADS * HDIM];

// ---------------- low-level helpers ----------------
__device__ __forceinline__ uint32_t smem_u32(const void* p) {
    uint32_t a;
    asm("{ .reg .u64 t; cvta.to.shared.u64 t, %1; cvt.u32.u64 %0, t; }" : "=r"(a) : "l"(p));
    return a;
}
__device__ __forceinline__ void cp_async16(uint32_t dst, const void* src) {
    asm volatile("cp.async.cg.shared.global [%0], [%1], 16;" :: "r"(dst), "l"(src));
}
__device__ __forceinline__ void cp_commit() { asm volatile("cp.async.commit_group;"); }
__device__ __forceinline__ void cp_wait1()  { asm volatile("cp.async.wait_group 1;"); }
__device__ __forceinline__ void cp_wait0()  { asm volatile("cp.async.wait_group 0;"); }

__device__ __forceinline__ void ldsm_x4(uint32_t& r0, uint32_t& r1, uint32_t& r2, uint32_t& r3,
                                        uint32_t addr) {
    asm volatile("ldmatrix.sync.aligned.m8n8.x4.shared.b16 {%0,%1,%2,%3}, [%4];"
                 : "=r"(r0), "=r"(r1), "=r"(r2), "=r"(r3) : "r"(addr));
}
__device__ __forceinline__ void ldsm_x4t(uint32_t& r0, uint32_t& r1, uint32_t& r2, uint32_t& r3,
                                         uint32_t addr) {
    asm volatile("ldmatrix.sync.aligned.m8n8.x4.trans.shared.b16 {%0,%1,%2,%3}, [%4];"
                 : "=r"(r0), "=r"(r1), "=r"(r2), "=r"(r3) : "r"(addr));
}
__device__ __forceinline__ void mma_bf16(float* c, const uint32_t* a, const uint32_t* b) {
    asm volatile("mma.sync.aligned.m16n8k16.row.col.f32.bf16.bf16.f32 "
                 "{%0,%1,%2,%3},{%4,%5,%6,%7},{%8,%9},{%0,%1,%2,%3};"
                 : "+f"(c[0]), "+f"(c[1]), "+f"(c[2]), "+f"(c[3])
                 : "r"(a[0]), "r"(a[1]), "r"(a[2]), "r"(a[3]), "r"(b[0]), "r"(b[1]));
}
__device__ __forceinline__ void split_bf16(float x, __nv_bfloat16& h, __nv_bfloat16& l) {
    h = __float2bfloat16(x);
    l = __float2bfloat16(x - __bfloat162float(h));
}
__device__ __forceinline__ uint32_t pack_bf(float a, float b) {
    __nv_bfloat162 v(__float2bfloat16(a), __float2bfloat16(b));
    return *reinterpret_cast<uint32_t*>(&v);
}

// ================= split-bf16 GEMM (unchanged from R4) =================
#define LDH 40
#define PLANE_B (128 * LDH * 2)
#define STAGE_B (4 * PLANE_B)
#define NSTAGE 3
#define GEMM_SMEM (NSTAGE * STAGE_B)

__global__ __launch_bounds__(256) void gemm_bf16_kernel(
    const __nv_bfloat16* __restrict__ Ah, const __nv_bfloat16* __restrict__ Al,
    const __nv_bfloat16* __restrict__ Bh, const __nv_bfloat16* __restrict__ Bl,
    float* __restrict__ C, int Kdim, size_t b_zstride, int ldc, int czcol)
{
    extern __shared__ char smem[];
    const uint32_t sbase = smem_u32(smem);
    const int tid = threadIdx.x;
    const int m0 = blockIdx.x * 128, n0b = blockIdx.y * 128, z = blockIdx.z;
    const __nv_bfloat16* Ahm = Ah + (size_t)m0 * Kdim;
    const __nv_bfloat16* Alm = Al + (size_t)m0 * Kdim;
    const __nv_bfloat16* Bhz = Bh + (size_t)z * b_zstride + (size_t)n0b * Kdim;
    const __nv_bfloat16* Blz = Bl + (size_t)z * b_zstride + (size_t)n0b * Kdim;
    const int ccol = z * czcol + n0b;
    const int NK = Kdim / 32;

    const int wid = tid >> 5, lane = tid & 31;
    const int wm = wid & 1, wn = wid >> 1;
    const int g = lane >> 2, t4 = lane & 3;

    auto issue_stage = [&](int s, int kt) {
        const int k0 = kt * 32;
        #pragma unroll
        for (int i = 0; i < 2; i++) {
            int idx = tid + i * 256;
            int r = idx >> 2, c = idx & 3;
            size_t goff = (size_t)r * Kdim + k0 + c * 8;
            uint32_t d = sbase + s * STAGE_B + r * (LDH * 2) + c * 16;
            cp_async16(d,               Ahm + goff);
            cp_async16(d + PLANE_B,     Alm + goff);
            cp_async16(d + 2 * PLANE_B, Bhz + goff);
            cp_async16(d + 3 * PLANE_B, Blz + goff);
        }
    };

    float acc[4][4][4];
    #pragma unroll
    for (int i = 0; i < 4; i++)
        #pragma unroll
        for (int j = 0; j < 4; j++)
            #pragma unroll
            for (int r = 0; r < 4; r++) acc[i][j][r] = 0.f;

    const int arow = wm * 64 + (lane & 7) + ((lane >> 3) & 1) * 8;
    const int akof = ((lane >> 4) & 1) * 8;
    const int brow = wn * 32 + (lane & 7) + ((lane >> 4) & 1) * 8;
    const int bkof = ((lane >> 3) & 1) * 8;

    issue_stage(0, 0); cp_commit();
    issue_stage(1, 1); cp_commit();

    for (int kt = 0; kt < NK; kt++) {
        cp_wait1();
        __syncthreads();
        if (kt + 2 < NK) issue_stage((kt + 2) % NSTAGE, kt + 2);
        cp_commit();

        const uint32_t st = sbase + (kt % NSTAGE) * STAGE_B;
        #pragma unroll
        for (int ks = 0; ks < 2; ks++) {
            uint32_t ah[4][4], al[4][4], bh[4][2], bl[4][2];
            #pragma unroll
            for (int i = 0; i < 4; i++) {
                uint32_t ad = st + (arow + i * 16) * (LDH * 2) + (ks * 16 + akof) * 2;
                ldsm_x4(ah[i][0], ah[i][1], ah[i][2], ah[i][3], ad);
                ldsm_x4(al[i][0], al[i][1], al[i][2], al[i][3], ad + PLANE_B);
            }
            #pragma unroll
            for (int jp = 0; jp < 2; jp++) {
                uint32_t bd = st + 2 * PLANE_B + (brow + jp * 16) * (LDH * 2) + (ks * 16 + bkof) * 2;
                uint32_t r0, r1, r2, r3;
                ldsm_x4(r0, r1, r2, r3, bd);
                bh[2 * jp][0] = r0; bh[2 * jp][1] = r1;
                bh[2 * jp + 1][0] = r2; bh[2 * jp + 1][1] = r3;
                ldsm_x4(r0, r1, r2, r3, bd + PLANE_B);
                bl[2 * jp][0] = r0; bl[2 * jp][1] = r1;
                bl[2 * jp + 1][0] = r2; bl[2 * jp + 1][1] = r3;
            }
            #pragma unroll
            for (int i = 0; i < 4; i++)
                #pragma unroll
                for (int j = 0; j < 4; j++) {
                    mma_bf16(acc[i][j], ah[i], bh[j]);
                    mma_bf16(acc[i][j], ah[i], bl[j]);
                    mma_bf16(acc[i][j], al[i], bh[j]);
                }
        }
    }

    #pragma unroll
    for (int i = 0; i < 4; i++) {
        const int r0 = m0 + wm * 64 + i * 16 + g;
        #pragma unroll
        for (int j = 0; j < 4; j++) {
            const int c0 = ccol + wn * 32 + j * 8 + t4 * 2;
            *reinterpret_cast<float2*>(&C[(size_t)r0 * ldc + c0]) =
                make_float2(acc[i][j][0], acc[i][j][1]);
            *reinterpret_cast<float2*>(&C[(size_t)(r0 + 8) * ldc + c0]) =
                make_float2(acc[i][j][2], acc[i][j][3]);
        }
    }
}

// ================= x -> bf16 hi/lo planes =================
__global__ __launch_bounds__(256) void convert_x_kernel(const float* __restrict__ x)
{
    size_t i = ((size_t)blockIdx.x * 256 + threadIdx.x) * 4;
    float4 v = *reinterpret_cast<const float4*>(x + i);
    __nv_bfloat16 h[4], l[4];
    split_bf16(v.x, h[0], l[0]); split_bf16(v.y, h[1], l[1]);
    split_bf16(v.z, h[2], l[2]); split_bf16(v.w, h[3], l[3]);
    *reinterpret_cast<__nv_bfloat162*>(g_xh + i)     = __nv_bfloat162(h[0], h[1]);
    *reinterpret_cast<__nv_bfloat162*>(g_xh + i + 2) = __nv_bfloat162(h[2], h[3]);
    *reinterpret_cast<__nv_bfloat162*>(g_xl + i)     = __nv_bfloat162(l[0], l[1]);
    *reinterpret_cast<__nv_bfloat162*>(g_xl + i + 2) = __nv_bfloat162(l[2], l[3]);
}

// ================= transpose + convert =================
__global__ __launch_bounds__(256) void transpose_conv_kernel(
    const float* __restrict__ in, __nv_bfloat16* __restrict__ outh,
    __nv_bfloat16* __restrict__ outl, int R, int C)
{
    __shared__ float t[32][33];
    size_t zo = (size_t)blockIdx.z * R * C;
    int c0 = blockIdx.x * 32, r0 = blockIdx.y * 32;
    int tx = threadIdx.x & 31, ty = threadIdx.x >> 5;
    #pragma unroll
    for (int i = 0; i < 32; i += 8)
        t[ty + i][tx] = in[zo + (size_t)(r0 + ty + i) * C + c0 + tx];
    __syncthreads();
    #pragma unroll
    for (int i = 0; i < 32; i += 8) {
        float v = t[tx][ty + i];
        __nv_bfloat16 h, l;
        split_bf16(v, h, l);
        size_t o = zo + (size_t)(c0 + ty + i) * R + r0 + tx;
        outh[o] = h;
        outl[o] = l;
    }
}

// ================= RMS-norm (+scale) (+RoPE) -> bf16 hi/lo planes =================
__device__ __forceinline__ void rope_apply(float v[8], int lane, int pos)
{
    #pragma unroll
    for (int j = 0; j < 4; j++) {
        int hh = lane + 32 * j;
        float ts = powf(10000.0f, (float)hh * (1.0f / 128.0f));
        float arg = (float)pos / ts;
        float sn, cs;
        sincosf(arg, &sn, &cs);
        float f = v[j], s = v[j + 4];
        v[j]     = f * cs - s * sn;
        v[j + 4] = s * cs + f * sn;
    }
}

__global__ __launch_bounds__(256) void norm_rope_q_kernel(const float* __restrict__ qscale,
                                                          const int* __restrict__ segpos)
{
    int row  = blockIdx.x * 8 + (threadIdx.x >> 5);
    int lane = threadIdx.x & 31;
    int t = row >> 4;
    const float* p = g_q + (size_t)row * HDIM;

    float v[8]; float ss = 0.f;
    #pragma unroll
    for (int j = 0; j < 8; j++) { v[j] = p[lane + 32 * j]; ss += v[j] * v[j]; }
    #pragma unroll
    for (int o = 16; o > 0; o >>= 1) ss += __shfl_xor_sync(0xffffffffu, ss, o);
    float rstd = rsqrtf(ss * (1.0f / 256.0f) + EPS);

    #pragma unroll
    for (int j = 0; j < 8; j++) {
        int h = lane + 32 * j;
        v[j] = v[j] * rstd * (1.0f + qscale[h]);
    }
    rope_apply(v, lane, segpos[t]);
    #pragma unroll
    for (int j = 0; j < 8; j++) {
        int h = lane + 32 * j;
        __nv_bfloat16 hh, ll;
        split_bf16(v[j], hh, ll);
        g_qh[(size_t)row * HDIM + h] = hh;
        g_ql[(size_t)row * HDIM + h] = ll;
    }
}

__global__ __launch_bounds__(256) void norm_rope_kv_kernel(const float* __restrict__ kscale,
                                                           const int* __restrict__ segpos)
{
    int row  = blockIdx.x * 8 + (threadIdx.x >> 5);
    int lane = threadIdx.x & 31;
    int t    = row >> 4;
    int head = row & 15;
    const float* p = g_kv + (size_t)row * HDIM;

    float v[8]; float ss = 0.f;
    #pragma unroll
    for (int j = 0; j < 8; j++) { v[j] = p[lane + 32 * j]; ss += v[j] * v[j]; }
    #pragma unroll
    for (int o = 16; o > 0; o >>= 1) ss += __shfl_xor_sync(0xffffffffu, ss, o);
    float rstd = rsqrtf(ss * (1.0f / 256.0f) + EPS);

    if (head < 8) {
        #pragma unroll
        for (int j = 0; j < 8; j++) {
            int h = lane + 32 * j;
            v[j] = v[j] * rstd * (1.0f + kscale[h]);
        }
        rope_apply(v, lane, segpos[t]);
    } else {
        #pragma unroll
        for (int j = 0; j < 8; j++) v[j] *= rstd;
    }
    #pragma unroll
    for (int j = 0; j < 8; j++) {
        int h = lane + 32 * j;
        __nv_bfloat16 hh, ll;
        split_bf16(v[j], hh, ll);
        g_kvh[(size_t)row * HDIM + h] = hh;
        g_kvl[(size_t)row * HDIM + h] = ll;
    }
}

// ================= tensor-core flash attention =================
// Block: 64 q-rows x 2 heads (sharing one kv head). 8 warps: warp = (head, 16 rows).
// 32-key chunks, split-bf16 3-term for both QK^T and PV.
#define SROWB 528                 // 264 halves per smem row
#define QPL 33792                 // 64 * 528
#define KPL 16896                 // 32 * 528
#define ATTN_SMEM (4 * QPL + 4 * KPL)   // 202752 B

__global__ __launch_bounds__(256, 1) void attn_mma_kernel()
{
    extern __shared__ char smc[];
    const uint32_t sb = smem_u32(smc);
    const int tid = threadIdx.x;
    const int wid = tid >> 5, lane = tid & 31;
    const int t0 = blockIdx.x * 64;
    const int hp = blockIdx.y;            // kv head
    const int hloc = wid >> 2;            // 0/1
    const int n = 2 * hp + hloc;          // q head
    const int R = (wid & 3) * 16;
    const int g = lane >> 2, t4 = lane & 3;

    const uint32_t sQh = sb + hloc * QPL;
    const uint32_t sQl = sb + 2 * QPL + hloc * QPL;
    const uint32_t sK0 = sb + 4 * QPL;    // Kh | Kl | Vh | Vl

    // ---- load Q (both heads, hi+lo) ----
    #pragma unroll
    for (int i = 0; i < 32; i++) {
        int idx = tid + i * 256;
        int pl = idx >> 12;               // 0 hi, 1 lo
        int hh = (idx >> 11) & 1;
        int r = (idx >> 5) & 63, c = idx & 31;
        const __nv_bfloat16* src = (pl ? g_ql : g_qh) +
            ((size_t)(t0 + r) * 16 + 2 * hp + hh) * 256 + c * 8;
        cp_async16(sb + pl * (2 * QPL) + hh * QPL + r * SROWB + c * 16, src);
    }
    cp_commit();

    float o[32][4];
    #pragma unroll
    for (int i = 0; i < 32; i++)
        #pragma unroll
        for (int c = 0; c < 4; c++) o[i][c] = 0.f;
    float m2[2] = {-1e29f, -1e29f}, l2[2] = {0.f, 0.f};

    int s_lo = t0 - (WINDOW - 1); if (s_lo < 0) s_lo = 0; s_lo &= ~31;

    // ldmatrix byte-offset bases
    const int aoff = (R + (lane & 7) + ((lane >> 3) & 1) * 8) * SROWB + ((lane >> 4) & 1) * 16;
    const int koff = (((lane >> 4) & 1) * 8 + (lane & 7)) * SROWB + ((lane >> 3) & 1) * 16;
    const int voff = (((lane >> 3) & 1) * 8 + (lane & 7)) * SROWB + ((lane >> 4) & 1) * 16;

    for (int sc0 = s_lo; sc0 <= t0 + 63; sc0 += 32) {
        __syncthreads();   // previous chunk's compute done before overwrite
        #pragma unroll
        for (int i = 0; i < 16; i++) {
            int idx = tid + i * 256;
            int pl = idx >> 10;           // 0 Kh, 1 Kl, 2 Vh, 3 Vl
            int r = (idx >> 5) & 31, c = idx & 31;
            const __nv_bfloat16* base = ((pl & 1) ? g_kvl : g_kvh);
            int vrow = (pl >= 2) ? 8 : 0;
            const __nv_bfloat16* src = base +
                ((size_t)(sc0 + r) * 16 + vrow + hp) * 256 + c * 8;
            cp_async16(sK0 + pl * KPL + r * SROWB + c * 16, src);
        }
        cp_commit();
        cp_wait0();
        __syncthreads();

        // ---- QK^T : S[16 rows][32 keys], 3-term split ----
        float s[4][4];
        #pragma unroll
        for (int j = 0; j < 4; j++)
            #pragma unroll
            for (int c = 0; c < 4; c++) s[j][c] = 0.f;

        #pragma unroll 4
        for (int hs = 0; hs < 16; hs++) {
            uint32_t qh[4], ql[4];
            ldsm_x4(qh[0], qh[1], qh[2], qh[3], sQh + aoff + hs * 32);
            ldsm_x4(ql[0], ql[1], ql[2], ql[3], sQl + aoff + hs * 32);
            #pragma unroll
            for (int p = 0; p < 2; p++) {
                uint32_t kh[4], kl[4];
                ldsm_x4(kh[0], kh[1], kh[2], kh[3], sK0 + koff + p * 16 * SROWB + hs * 32);
                ldsm_x4(kl[0], kl[1], kl[2], kl[3], sK0 + KPL + koff + p * 16 * SROWB + hs * 32);
                mma_bf16(s[2 * p], qh, kh);     mma_bf16(s[2 * p], qh, kl);
                mma_bf16(s[2 * p], ql, kh);
                mma_bf16(s[2 * p + 1], qh, kh + 2); mma_bf16(s[2 * p + 1], qh, kl + 2);
                mma_bf16(s[2 * p + 1], ql, kh + 2);
            }
        }

        // ---- soft-cap + mask ----
        #pragma unroll
        for (int j = 0; j < 4; j++)
            #pragma unroll
            for (int c = 0; c < 4; c++) {
                int tq = t0 + R + g + ((c >> 1) << 3);
                int sk = sc0 + j * 8 + 2 * t4 + (c & 1);
                float xx = s[j][c] * (1.0f / SOFT_CAP);
                xx = fminf(fmaxf(xx, -10.f), 10.f);
                float e = __expf(2.0f * xx);
                float val = SOFT_CAP * __fdividef(e - 1.0f, e + 1.0f);
                bool ok = (sk <= tq) && (sk > tq - WINDOW);
                s[j][c] = ok ? val : -1e30f;
            }

        // ---- online softmax (rows g and g+8) ----
        float mx0 = -1e30f, mx1 = -1e30f;
        #pragma unroll
        for (int j = 0; j < 4; j++) {
            mx0 = fmaxf(mx0, fmaxf(s[j][0], s[j][1]));
            mx1 = fmaxf(mx1, fmaxf(s[j][2], s[j][3]));
        }
        mx0 = fmaxf(mx0, __shfl_xor_sync(0xffffffffu, mx0, 1));
        mx0 = fmaxf(mx0, __shfl_xor_sync(0xffffffffu, mx0, 2));
        mx1 = fmaxf(mx1, __shfl_xor_sync(0xffffffffu, mx1, 1));
        mx1 = fmaxf(mx1, __shfl_xor_sync(0xffffffffu, mx1, 2));
        float mn0 = fmaxf(m2[0], mx0), mn1 = fmaxf(m2[1], mx1);
        float a0 = __expf(m2[0] - mn0), a1 = __expf(m2[1] - mn1);
        float sum0 = 0.f, sum1 = 0.f;
        #pragma unroll
        for (int j = 0; j < 4; j++) {
            s[j][0] = __expf(s[j][0] - mn0); sum0 += s[j][0];
            s[j][1] = __expf(s[j][1] - mn0); sum0 += s[j][1];
            s[j][2] = __expf(s[j][2] - mn1); sum1 += s[j][2];
            s[j][3] = __expf(s[j][3] - mn1); sum1 += s[j][3];
        }
        sum0 += __shfl_xor_sync(0xffffffffu, sum0, 1);
        sum0 += __shfl_xor_sync(0xffffffffu, sum0, 2);
        sum1 += __shfl_xor_sync(0xffffffffu, sum1, 1);
        sum1 += __shfl_xor_sync(0xffffffffu, sum1, 2);
        l2[0] = l2[0] * a0 + sum0;
        l2[1] = l2[1] * a1 + sum1;
        m2[0] = mn0; m2[1] = mn1;
        if (a0 != 1.f || a1 != 1.f) {
            #pragma unroll
            for (int i = 0; i < 32; i++) {
                o[i][0] *= a0; o[i][1] *= a0;
                o[i][2] *= a1; o[i][3] *= a1;
            }
        }

        // ---- PV : O += P @ V, 3-term split; P frags built in-register ----
        #pragma unroll
        for (int ks = 0; ks < 2; ks++) {
            const int jb = 2 * ks;
            uint32_t aph[4], apl[4];
            {
                float p00 = s[jb][0],  p01 = s[jb][1],  p02 = s[jb][2],  p03 = s[jb][3];
                float p10 = s[jb+1][0], p11 = s[jb+1][1], p12 = s[jb+1][2], p13 = s[jb+1][3];
                __nv_bfloat16 h, l;
                float r00, r01, r02, r03, r10, r11, r12, r13;
                split_bf16(p00, h, l); r00 = __bfloat162float(l);
                split_bf16(p01, h, l); r01 = __bfloat162float(l);
                split_bf16(p02, h, l); r02 = __bfloat162float(l);
                split_bf16(p03, h, l); r03 = __bfloat162float(l);
                split_bf16(p10, h, l); r10 = __bfloat162float(l);
                split_bf16(p11, h, l); r11 = __bfloat162float(l);
                split_bf16(p12, h, l); r12 = __bfloat162float(l);
                split_bf16(p13, h, l); r13 = __bfloat162float(l);
                aph[0] = pack_bf(p00, p01); aph[1] = pack_bf(p02, p03);
                aph[2] = pack_bf(p10, p11); aph[3] = pack_bf(p12, p13);
                apl[0] = pack_bf(r00, r01); apl[1] = pack_bf(r02, r03);
                apl[2] = pack_bf(r10, r11); apl[3] = pack_bf(r12, r13);
            }
            #pragma unroll
            for (int u = 0; u < 16; u++) {
                uint32_t vh[4], vl[4];
                uint32_t va = sK0 + 2 * KPL + voff + ks * 16 * SROWB + u * 32;
                ldsm_x4t(vh[0], vh[1], vh[2], vh[3], va);
                ldsm_x4t(vl[0], vl[1], vl[2], vl[3], va + KPL);
                mma_bf16(o[2 * u], aph, vh);     mma_bf16(o[2 * u], aph, vl);
                mma_bf16(o[2 * u], apl, vh);
                mma_bf16(o[2 * u + 1], aph, vh + 2); mma_bf16(o[2 * u + 1], aph, vl + 2);
                mma_bf16(o[2 * u + 1], apl, vh + 2);
            }
        }
    }

    // ---- epilogue: normalize, split, write enc planes ----
    float inv0 = __fdividef(1.f, l2[0]);
    float inv1 = __fdividef(1.f, l2[1]);
    const int row0 = t0 + R + g, row1 = row0 + 8;
    #pragma unroll
    for (int ht = 0; ht < 32; ht++) {
        int h = ht * 8 + 2 * t4;
        float v0 = o[ht][0] * inv0, v1 = o[ht][1] * inv0;
        float v2 = o[ht][2] * inv1, v3 = o[ht][3] * inv1;
        __nv_bfloat16 h0, l0, h1, l1, h2, l2b, h3, l3;
        split_bf16(v0, h0, l0); split_bf16(v1, h1, l1);
        split_bf16(v2, h2, l2b); split_bf16(v3, h3, l3);
        size_t a0 = ((size_t)row0 * 16 + n) * 256 + h;
        size_t a1 = ((size_t)row1 * 16 + n) * 256 + h;
        *reinterpret_cast<__nv_bfloat162*>(g_ench + a0) = __nv_bfloat162(h0, h1);
        *reinterpret_cast<__nv_bfloat162*>(g_encl + a0) = __nv_bfloat162(l0, l1);
        *reinterpret_cast<__nv_bfloat162*>(g_ench + a1) = __nv_bfloat162(h2, h3);
        *reinterpret_cast<__nv_bfloat162*>(g_encl + a1) = __nv_bfloat162(l2b, l3);
    }
}

// ================= launch =================
extern "C" void kernel_launch(void* const* d_in, const int* in_sizes, int n_in,
                              void* d_out, int out_size)
{
    const float* x       = (const float*)d_in[0];
    const int*   segpos  = (const int*)  d_in[1];
    const float* w_q     = (const float*)d_in[3];
    const float* w_kv    = (const float*)d_in[4];
    const float* w_out   = (const float*)d_in[5];
    const float* q_scale = (const float*)d_in[6];
    const float* k_scale = (const float*)d_in[7];
    float*       out     = (float*)d_out;

    __nv_bfloat16 *xh, *xl, *wqh, *wql, *wkvh, *wkvl, *woh, *wol, *ench, *encl;
    float *gq, *gkv;
    cudaGetSymbolAddress((void**)&xh,   g_xh);
    cudaGetSymbolAddress((void**)&xl,   g_xl);
    cudaGetSymbolAddress((void**)&wqh,  g_wqh);
    cudaGetSymbolAddress((void**)&wql,  g_wql);
    cudaGetSymbolAddress((void**)&wkvh, g_wkvh);
    cudaGetSymbolAddress((void**)&wkvl, g_wkvl);
    cudaGetSymbolAddress((void**)&woh,  g_woh);
    cudaGetSymbolAddress((void**)&wol,  g_wol);
    cudaGetSymbolAddress((void**)&ench, g_ench);
    cudaGetSymbolAddress((void**)&encl, g_encl);
    cudaGetSymbolAddress((void**)&gq,   g_q);
    cudaGetSymbolAddress((void**)&gkv,  g_kv);

    const dim3 blk(256);

    // 0. precision prep
    convert_x_kernel<<<(T_SEQ * D_MODEL) / (256 * 4), blk>>>(x);
    transpose_conv_kernel<<<dim3(HDIM / 32, D_MODEL / 32, 16), blk>>>(w_q,  wqh, wql, D_MODEL, HDIM);
    transpose_conv_kernel<<<dim3(HDIM / 32, D_MODEL / 32, 16), blk>>>(w_kv, wkvh, wkvl, D_MODEL, HDIM);
    transpose_conv_kernel<<<dim3(D_MODEL / 32, (N_HEADS * HDIM) / 32, 1), blk>>>(
        w_out, woh, wol, N_HEADS * HDIM, D_MODEL);

    // 1. projections
    cudaFuncSetAttribute(gemm_bf16_kernel, cudaFuncAttributeMaxDynamicSharedMemorySize, GEMM_SMEM);
    gemm_bf16_kernel<<<dim3(T_SEQ / 128, HDIM / 128, 16), blk, GEMM_SMEM>>>(
        xh, xl, wqh, wql, gq, D_MODEL, (size_t)HDIM * D_MODEL, N_HEADS * HDIM, HDIM);
    gemm_bf16_kernel<<<dim3(T_SEQ / 128, HDIM / 128, 16), blk, GEMM_SMEM>>>(
        xh, xl, wkvh, wkvl, gkv, D_MODEL, (size_t)HDIM * D_MODEL, 16 * HDIM, HDIM);

    // 2. norms + rope -> bf16 hi/lo planes
    norm_rope_q_kernel <<<(T_SEQ * N_HEADS) / 8, blk>>>(q_scale, segpos);
    norm_rope_kv_kernel<<<(T_SEQ * 16) / 8,      blk>>>(k_scale, segpos);

    // 3. attention (tensor cores)
    cudaFuncSetAttribute(attn_mma_kernel, cudaFuncAttributeMaxDynamicSharedMemorySize, ATTN_SMEM);
    attn_mma_kernel<<<dim3(T_SEQ / 64, K_HEADS), blk, ATTN_SMEM>>>();

    // 4. output projection
    gemm_bf16_kernel<<<dim3(T_SEQ / 128, D_MODEL / 128, 1), blk, GEMM_SMEM>>>(
        ench, encl, woh, wol, out, N_HEADS * HDIM, 0, D_MODEL, 0);
}

// round 6
// speedup vs baseline: 1.5692x; 1.5692x over previous
#include <cuda_runtime.h>
#include <cuda_bf16.h>
#include <math.h>
#include <stdint.h>

// ---------------- problem constants ----------------
#define T_SEQ   2048
#define D_MODEL 3072
#define N_HEADS 16
#define K_HEADS 8
#define HDIM    256
#define WINDOW  1024
#define SOFT_CAP 50.0f
#define EPS 1e-6f

// ---------------- scratch (static device globals) ----------------
__device__ float g_q  [(size_t)T_SEQ * N_HEADS * HDIM];
__device__ float g_kv [(size_t)T_SEQ * 16 * HDIM];
__device__ __nv_bfloat16 g_xh [(size_t)T_SEQ * D_MODEL];
__device__ __nv_bfloat16 g_xl [(size_t)T_SEQ * D_MODEL];
__device__ __nv_bfloat16 g_qh [(size_t)T_SEQ * N_HEADS * HDIM];
__device__ __nv_bfloat16 g_ql [(size_t)T_SEQ * N_HEADS * HDIM];
__device__ __nv_bfloat16 g_kvh[(size_t)T_SEQ * 16 * HDIM];
__device__ __nv_bfloat16 g_kvl[(size_t)T_SEQ * 16 * HDIM];
__device__ __nv_bfloat16 g_wqh [(size_t)N_HEADS * HDIM * D_MODEL];
__device__ __nv_bfloat16 g_wql [(size_t)N_HEADS * HDIM * D_MODEL];
__device__ __nv_bfloat16 g_wkvh[(size_t)16 * HDIM * D_MODEL];
__device__ __nv_bfloat16 g_wkvl[(size_t)16 * HDIM * D_MODEL];
__device__ __nv_bfloat16 g_woh [(size_t)D_MODEL * N_HEADS * HDIM];
__device__ __nv_bfloat16 g_wol [(size_t)D_MODEL * N_HEADS * HDIM];
__device__ __nv_bfloat16 g_ench[(size_t)T_SEQ * N_HEADS * HDIM];
__device__ __nv_bfloat16 g_encl[(size_t)T_SEQ * N_HEADS * HDIM];

// ---------------- low-level helpers ----------------
__device__ __forceinline__ uint32_t smem_u32(const void* p) {
    uint32_t a;
    asm("{ .reg .u64 t; cvta.to.shared.u64 t, %1; cvt.u32.u64 %0, t; }" : "=r"(a) : "l"(p));
    return a;
}
__device__ __forceinline__ void cp_async16(uint32_t dst, const void* src) {
    asm volatile("cp.async.cg.shared.global [%0], [%1], 16;" :: "r"(dst), "l"(src));
}
__device__ __forceinline__ void cp_commit() { asm volatile("cp.async.commit_group;"); }
__device__ __forceinline__ void cp_wait1()  { asm volatile("cp.async.wait_group 1;"); }

__device__ __forceinline__ void ldsm_x4(uint32_t& r0, uint32_t& r1, uint32_t& r2, uint32_t& r3,
                                        uint32_t addr) {
    asm volatile("ldmatrix.sync.aligned.m8n8.x4.shared.b16 {%0,%1,%2,%3}, [%4];"
                 : "=r"(r0), "=r"(r1), "=r"(r2), "=r"(r3) : "r"(addr));
}
__device__ __forceinline__ void ldsm_x4t(uint32_t& r0, uint32_t& r1, uint32_t& r2, uint32_t& r3,
                                         uint32_t addr) {
    asm volatile("ldmatrix.sync.aligned.m8n8.x4.trans.shared.b16 {%0,%1,%2,%3}, [%4];"
                 : "=r"(r0), "=r"(r1), "=r"(r2), "=r"(r3) : "r"(addr));
}
__device__ __forceinline__ void mma_bf16(float* c, const uint32_t* a, const uint32_t* b) {
    asm volatile("mma.sync.aligned.m16n8k16.row.col.f32.bf16.bf16.f32 "
                 "{%0,%1,%2,%3},{%4,%5,%6,%7},{%8,%9},{%0,%1,%2,%3};"
                 : "+f"(c[0]), "+f"(c[1]), "+f"(c[2]), "+f"(c[3])
                 : "r"(a[0]), "r"(a[1]), "r"(a[2]), "r"(a[3]), "r"(b[0]), "r"(b[1]));
}
__device__ __forceinline__ void split_bf16(float x, __nv_bfloat16& h, __nv_bfloat16& l) {
    h = __float2bfloat16(x);
    l = __float2bfloat16(x - __bfloat162float(h));
}

// ================= split-bf16 GEMM (unchanged, known-good) =================
#define LDH 40
#define PLANE_B (128 * LDH * 2)
#define STAGE_B (4 * PLANE_B)
#define NSTAGE 3
#define GEMM_SMEM (NSTAGE * STAGE_B)

__global__ __launch_bounds__(256) void gemm_bf16_kernel(
    const __nv_bfloat16* __restrict__ Ah, const __nv_bfloat16* __restrict__ Al,
    const __nv_bfloat16* __restrict__ Bh, const __nv_bfloat16* __restrict__ Bl,
    float* __restrict__ C, int Kdim, size_t b_zstride, int ldc, int czcol)
{
    extern __shared__ char smem[];
    const uint32_t sbase = smem_u32(smem);
    const int tid = threadIdx.x;
    const int m0 = blockIdx.x * 128, n0b = blockIdx.y * 128, z = blockIdx.z;
    const __nv_bfloat16* Ahm = Ah + (size_t)m0 * Kdim;
    const __nv_bfloat16* Alm = Al + (size_t)m0 * Kdim;
    const __nv_bfloat16* Bhz = Bh + (size_t)z * b_zstride + (size_t)n0b * Kdim;
    const __nv_bfloat16* Blz = Bl + (size_t)z * b_zstride + (size_t)n0b * Kdim;
    const int ccol = z * czcol + n0b;
    const int NK = Kdim / 32;

    const int wid = tid >> 5, lane = tid & 31;
    const int wm = wid & 1, wn = wid >> 1;
    const int g = lane >> 2, t4 = lane & 3;

    auto issue_stage = [&](int s, int kt) {
        const int k0 = kt * 32;
        #pragma unroll
        for (int i = 0; i < 2; i++) {
            int idx = tid + i * 256;
            int r = idx >> 2, c = idx & 3;
            size_t goff = (size_t)r * Kdim + k0 + c * 8;
            uint32_t d = sbase + s * STAGE_B + r * (LDH * 2) + c * 16;
            cp_async16(d,               Ahm + goff);
            cp_async16(d + PLANE_B,     Alm + goff);
            cp_async16(d + 2 * PLANE_B, Bhz + goff);
            cp_async16(d + 3 * PLANE_B, Blz + goff);
        }
    };

    float acc[4][4][4];
    #pragma unroll
    for (int i = 0; i < 4; i++)
        #pragma unroll
        for (int j = 0; j < 4; j++)
            #pragma unroll
            for (int r = 0; r < 4; r++) acc[i][j][r] = 0.f;

    const int arow = wm * 64 + (lane & 7) + ((lane >> 3) & 1) * 8;
    const int akof = ((lane >> 4) & 1) * 8;
    const int brow = wn * 32 + (lane & 7) + ((lane >> 4) & 1) * 8;
    const int bkof = ((lane >> 3) & 1) * 8;

    issue_stage(0, 0); cp_commit();
    issue_stage(1, 1); cp_commit();

    for (int kt = 0; kt < NK; kt++) {
        cp_wait1();
        __syncthreads();
        if (kt + 2 < NK) issue_stage((kt + 2) % NSTAGE, kt + 2);
        cp_commit();

        const uint32_t st = sbase + (kt % NSTAGE) * STAGE_B;
        #pragma unroll
        for (int ks = 0; ks < 2; ks++) {
            uint32_t ah[4][4], al[4][4], bh[4][2], bl[4][2];
            #pragma unroll
            for (int i = 0; i < 4; i++) {
                uint32_t ad = st + (arow + i * 16) * (LDH * 2) + (ks * 16 + akof) * 2;
                ldsm_x4(ah[i][0], ah[i][1], ah[i][2], ah[i][3], ad);
                ldsm_x4(al[i][0], al[i][1], al[i][2], al[i][3], ad + PLANE_B);
            }
            #pragma unroll
            for (int jp = 0; jp < 2; jp++) {
                uint32_t bd = st + 2 * PLANE_B + (brow + jp * 16) * (LDH * 2) + (ks * 16 + bkof) * 2;
                uint32_t r0, r1, r2, r3;
                ldsm_x4(r0, r1, r2, r3, bd);
                bh[2 * jp][0] = r0; bh[2 * jp][1] = r1;
                bh[2 * jp + 1][0] = r2; bh[2 * jp + 1][1] = r3;
                ldsm_x4(r0, r1, r2, r3, bd + PLANE_B);
                bl[2 * jp][0] = r0; bl[2 * jp][1] = r1;
                bl[2 * jp + 1][0] = r2; bl[2 * jp + 1][1] = r3;
            }
            #pragma unroll
            for (int i = 0; i < 4; i++)
                #pragma unroll
                for (int j = 0; j < 4; j++) {
                    mma_bf16(acc[i][j], ah[i], bh[j]);
                    mma_bf16(acc[i][j], ah[i], bl[j]);
                    mma_bf16(acc[i][j], al[i], bh[j]);
                }
        }
    }

    #pragma unroll
    for (int i = 0; i < 4; i++) {
        const int r0 = m0 + wm * 64 + i * 16 + g;
        #pragma unroll
        for (int j = 0; j < 4; j++) {
            const int c0 = ccol + wn * 32 + j * 8 + t4 * 2;
            *reinterpret_cast<float2*>(&C[(size_t)r0 * ldc + c0]) =
                make_float2(acc[i][j][0], acc[i][j][1]);
            *reinterpret_cast<float2*>(&C[(size_t)(r0 + 8) * ldc + c0]) =
                make_float2(acc[i][j][2], acc[i][j][3]);
        }
    }
}

// ================= x -> bf16 hi/lo planes =================
__global__ __launch_bounds__(256) void convert_x_kernel(const float* __restrict__ x)
{
    size_t i = ((size_t)blockIdx.x * 256 + threadIdx.x) * 4;
    float4 v = *reinterpret_cast<const float4*>(x + i);
    __nv_bfloat16 h[4], l[4];
    split_bf16(v.x, h[0], l[0]); split_bf16(v.y, h[1], l[1]);
    split_bf16(v.z, h[2], l[2]); split_bf16(v.w, h[3], l[3]);
    *reinterpret_cast<__nv_bfloat162*>(g_xh + i)     = __nv_bfloat162(h[0], h[1]);
    *reinterpret_cast<__nv_bfloat162*>(g_xh + i + 2) = __nv_bfloat162(h[2], h[3]);
    *reinterpret_cast<__nv_bfloat162*>(g_xl + i)     = __nv_bfloat162(l[0], l[1]);
    *reinterpret_cast<__nv_bfloat162*>(g_xl + i + 2) = __nv_bfloat162(l[2], l[3]);
}

// ================= transpose + convert =================
__global__ __launch_bounds__(256) void transpose_conv_kernel(
    const float* __restrict__ in, __nv_bfloat16* __restrict__ outh,
    __nv_bfloat16* __restrict__ outl, int R, int C)
{
    __shared__ float t[32][33];
    size_t zo = (size_t)blockIdx.z * R * C;
    int c0 = blockIdx.x * 32, r0 = blockIdx.y * 32;
    int tx = threadIdx.x & 31, ty = threadIdx.x >> 5;
    #pragma unroll
    for (int i = 0; i < 32; i += 8)
        t[ty + i][tx] = in[zo + (size_t)(r0 + ty + i) * C + c0 + tx];
    __syncthreads();
    #pragma unroll
    for (int i = 0; i < 32; i += 8) {
        float v = t[tx][ty + i];
        __nv_bfloat16 h, l;
        split_bf16(v, h, l);
        size_t o = zo + (size_t)(c0 + ty + i) * R + r0 + tx;
        outh[o] = h;
        outl[o] = l;
    }
}

// ================= RMS-norm (+scale) (+RoPE) -> bf16 hi/lo planes =================
__device__ __forceinline__ void rope_apply(float v[8], int lane, int pos)
{
    #pragma unroll
    for (int j = 0; j < 4; j++) {
        int hh = lane + 32 * j;
        float ts = powf(10000.0f, (float)hh * (1.0f / 128.0f));
        float arg = (float)pos / ts;
        float sn, cs;
        sincosf(arg, &sn, &cs);
        float f = v[j], s = v[j + 4];
        v[j]     = f * cs - s * sn;
        v[j + 4] = s * cs + f * sn;
    }
}

__global__ __launch_bounds__(256) void norm_rope_q_kernel(const float* __restrict__ qscale,
                                                          const int* __restrict__ segpos)
{
    int row  = blockIdx.x * 8 + (threadIdx.x >> 5);
    int lane = threadIdx.x & 31;
    int t = row >> 4;
    const float* p = g_q + (size_t)row * HDIM;

    float v[8]; float ss = 0.f;
    #pragma unroll
    for (int j = 0; j < 8; j++) { v[j] = p[lane + 32 * j]; ss += v[j] * v[j]; }
    #pragma unroll
    for (int o = 16; o > 0; o >>= 1) ss += __shfl_xor_sync(0xffffffffu, ss, o);
    float rstd = rsqrtf(ss * (1.0f / 256.0f) + EPS);

    #pragma unroll
    for (int j = 0; j < 8; j++) {
        int h = lane + 32 * j;
        v[j] = v[j] * rstd * (1.0f + qscale[h]);
    }
    rope_apply(v, lane, segpos[t]);
    #pragma unroll
    for (int j = 0; j < 8; j++) {
        int h = lane + 32 * j;
        __nv_bfloat16 hh, ll;
        split_bf16(v[j], hh, ll);
        g_qh[(size_t)row * HDIM + h] = hh;
        g_ql[(size_t)row * HDIM + h] = ll;
    }
}

__global__ __launch_bounds__(256) void norm_rope_kv_kernel(const float* __restrict__ kscale,
                                                           const int* __restrict__ segpos)
{
    int row  = blockIdx.x * 8 + (threadIdx.x >> 5);
    int lane = threadIdx.x & 31;
    int t    = row >> 4;
    int head = row & 15;
    const float* p = g_kv + (size_t)row * HDIM;

    float v[8]; float ss = 0.f;
    #pragma unroll
    for (int j = 0; j < 8; j++) { v[j] = p[lane + 32 * j]; ss += v[j] * v[j]; }
    #pragma unroll
    for (int o = 16; o > 0; o >>= 1) ss += __shfl_xor_sync(0xffffffffu, ss, o);
    float rstd = rsqrtf(ss * (1.0f / 256.0f) + EPS);

    if (head < 8) {
        #pragma unroll
        for (int j = 0; j < 8; j++) {
            int h = lane + 32 * j;
            v[j] = v[j] * rstd * (1.0f + kscale[h]);
        }
        rope_apply(v, lane, segpos[t]);
    } else {
        #pragma unroll
        for (int j = 0; j < 8; j++) v[j] *= rstd;
    }
    #pragma unroll
    for (int j = 0; j < 8; j++) {
        int h = lane + 32 * j;
        __nv_bfloat16 hh, ll;
        split_bf16(v[j], hh, ll);
        g_kvh[(size_t)row * HDIM + h] = hh;
        g_kvl[(size_t)row * HDIM + h] = ll;
    }
}

// ================= tensor-core flash attention, v2 =================
// CTA: 64 q-rows x 1 head; 8 warps = 4 row-groups x 2 halves (wc).
// QK^T: warp computes S[16 rows x 16 keys] (wc = key half), full 256-dim.
// Softmax: cross-warp max/sum exchange via smem. P -> smem bf16 hi/lo.
// PV: warp computes O[16 rows x 128 dims] (wc = dim half). Staggered K/V prefetch.
#define SROWB 528
#define QPL 33792                 // 64 * 528
#define KPL 16896                 // 32 * 528
#define PROWB 80                  // P plane row stride (40 halves)
#define PPL (64 * PROWB)          // 5120
#define ATTN_SMEM (2 * QPL + 4 * KPL + 2 * PPL + 1024)   // 146432

__global__ __launch_bounds__(256, 1) void attn_mma_kernel()
{
    extern __shared__ char smc[];
    const uint32_t sb = smem_u32(smc);
    const int tid = threadIdx.x;
    const int wid = tid >> 5, lane = tid & 31;
    const int t0 = blockIdx.x * 64;
    const int n  = blockIdx.y;           // q head
    const int hp = n >> 1;               // kv head
    const int wr = wid & 3, wc = wid >> 2;
    const int R  = wr * 16;
    const int g = lane >> 2, t4 = lane & 3;

    const uint32_t sQh = sb, sQl = sb + QPL;
    const uint32_t sKh = sb + 2 * QPL;
    const uint32_t sKl = sKh + KPL;
    const uint32_t sVh = sKh + 2 * KPL;
    const uint32_t sVl = sKh + 3 * KPL;
    const uint32_t sPh = sb + 2 * QPL + 4 * KPL;
    const uint32_t sPl = sPh + PPL;
    float* redmax = reinterpret_cast<float*>(smc + 2 * QPL + 4 * KPL + 2 * PPL);
    float* redsum = redmax + 128;

    // ---- load Q (hi+lo) ----
    #pragma unroll
    for (int i = 0; i < 16; i++) {
        int idx = tid + i * 256;
        int pl = idx >> 11;               // 0 hi, 1 lo
        int r = (idx >> 5) & 63, c = idx & 31;
        const __nv_bfloat16* src = (pl ? g_ql : g_qh) +
            ((size_t)(t0 + r) * 16 + n) * 256 + c * 8;
        cp_async16(sb + pl * QPL + r * SROWB + c * 16, src);
    }
    cp_commit();

    auto issue_K = [&](int sc0) {
        #pragma unroll
        for (int i = 0; i < 8; i++) {
            int idx = tid + i * 256;
            int pl = idx >> 10;           // 0 hi, 1 lo
            int r = (idx >> 5) & 31, c = idx & 31;
            const __nv_bfloat16* src = (pl ? g_kvl : g_kvh) +
                ((size_t)(sc0 + r) * 16 + hp) * 256 + c * 8;
            cp_async16(sKh + pl * KPL + r * SROWB + c * 16, src);
        }
    };
    auto issue_V = [&](int sc0) {
        #pragma unroll
        for (int i = 0; i < 8; i++) {
            int idx = tid + i * 256;
            int pl = idx >> 10;
            int r = (idx >> 5) & 31, c = idx & 31;
            const __nv_bfloat16* src = (pl ? g_kvl : g_kvh) +
                ((size_t)(sc0 + r) * 16 + 8 + hp) * 256 + c * 8;
            cp_async16(sVh + pl * KPL + r * SROWB + c * 16, src);
        }
    };

    float o[16][4];
    #pragma unroll
    for (int i = 0; i < 16; i++)
        #pragma unroll
        for (int c = 0; c < 4; c++) o[i][c] = 0.f;
    float m2[2] = {-1e29f, -1e29f}, l2[2] = {0.f, 0.f};

    int s_lo = t0 - (WINDOW - 1); if (s_lo < 0) s_lo = 0; s_lo &= ~31;

    // fragment offset bases (validated in R5)
    const int aoff  = (R + (lane & 7) + ((lane >> 3) & 1) * 8) * SROWB + ((lane >> 4) & 1) * 16;
    const int koff  = (((lane >> 4) & 1) * 8 + (lane & 7)) * SROWB + ((lane >> 3) & 1) * 16
                      + wc * 16 * SROWB;
    const int voff  = (((lane >> 3) & 1) * 8 + (lane & 7)) * SROWB + ((lane >> 4) & 1) * 16
                      + wc * 256;
    const int aoffP = (R + (lane & 7) + ((lane >> 3) & 1) * 8) * PROWB + ((lane >> 4) & 1) * 16;
    const int tq0 = t0 + R + g, tq1 = tq0 + 8;

    // wait for Q before prologue K/V issue ordering: issue K0,V0 now (groups after Q group)
    issue_K(s_lo); cp_commit();
    issue_V(s_lo); cp_commit();
    // groups pending: [Q, K0, V0] -> wait until <=1: Q and K0 done.

    asm volatile("cp.async.wait_group 1;");
    __syncthreads();

    for (int sc0 = s_lo; sc0 <= t0 + 63; sc0 += 32) {
        const bool has_next = (sc0 + 32 <= t0 + 63);

        // ---- QK^T: S[16 x 16] over full 256 dims ----
        float s[2][4];
        #pragma unroll
        for (int j = 0; j < 2; j++)
            #pragma unroll
            for (int c = 0; c < 4; c++) s[j][c] = 0.f;

        #pragma unroll 4
        for (int hs = 0; hs < 16; hs++) {
            uint32_t qh[4], ql[4], kh[4], kl[4];
            ldsm_x4(qh[0], qh[1], qh[2], qh[3], sQh + aoff + hs * 32);
            ldsm_x4(ql[0], ql[1], ql[2], ql[3], sQl + aoff + hs * 32);
            ldsm_x4(kh[0], kh[1], kh[2], kh[3], sKh + koff + hs * 32);
            ldsm_x4(kl[0], kl[1], kl[2], kl[3], sKl + koff + hs * 32);
            mma_bf16(s[0], qh, kh); mma_bf16(s[0], qh, kl); mma_bf16(s[0], ql, kh);
            mma_bf16(s[1], qh, kh + 2); mma_bf16(s[1], qh, kl + 2); mma_bf16(s[1], ql, kh + 2);
        }

        // ---- soft-cap + mask ----
        #pragma unroll
        for (int j = 0; j < 2; j++)
            #pragma unroll
            for (int c = 0; c < 4; c++) {
                int tq = (c >> 1) ? tq1 : tq0;
                int sk = sc0 + wc * 16 + j * 8 + 2 * t4 + (c & 1);
                float xx = s[j][c] * (1.0f / SOFT_CAP);
                xx = fminf(fmaxf(xx, -10.f), 10.f);
                float e = __expf(2.0f * xx);
                float val = SOFT_CAP * __fdividef(e - 1.0f, e + 1.0f);
                bool ok = (sk <= tq) && (sk > tq - WINDOW);
                s[j][c] = ok ? val : -1e30f;
            }

        // ---- local row max + exchange ----
        float mx0 = fmaxf(fmaxf(s[0][0], s[0][1]), fmaxf(s[1][0], s[1][1]));
        float mx1 = fmaxf(fmaxf(s[0][2], s[0][3]), fmaxf(s[1][2], s[1][3]));
        mx0 = fmaxf(mx0, __shfl_xor_sync(0xffffffffu, mx0, 1));
        mx0 = fmaxf(mx0, __shfl_xor_sync(0xffffffffu, mx0, 2));
        mx1 = fmaxf(mx1, __shfl_xor_sync(0xffffffffu, mx1, 1));
        mx1 = fmaxf(mx1, __shfl_xor_sync(0xffffffffu, mx1, 2));
        if (t4 == 0) {
            redmax[wc * 64 + R + g] = mx0;
            redmax[wc * 64 + R + g + 8] = mx1;
        }
        __syncthreads();                 // S done (K free), redmax visible

        if (has_next) issue_K(sc0 + 32);
        cp_commit();                     // pending: [V_i, K_{i+1}]

        float cm0 = fmaxf(mx0, redmax[(1 - wc) * 64 + R + g]);
        float cm1 = fmaxf(mx1, redmax[(1 - wc) * 64 + R + g + 8]);
        float mn0 = fmaxf(m2[0], cm0), mn1 = fmaxf(m2[1], cm1);
        float a0 = __expf(m2[0] - mn0), a1 = __expf(m2[1] - mn1);
        m2[0] = mn0; m2[1] = mn1;

        float sum0 = 0.f, sum1 = 0.f;
        #pragma unroll
        for (int j = 0; j < 2; j++) {
            s[j][0] = __expf(s[j][0] - mn0); sum0 += s[j][0];
            s[j][1] = __expf(s[j][1] - mn0); sum0 += s[j][1];
            s[j][2] = __expf(s[j][2] - mn1); sum1 += s[j][2];
            s[j][3] = __expf(s[j][3] - mn1); sum1 += s[j][3];
        }
        sum0 += __shfl_xor_sync(0xffffffffu, sum0, 1);
        sum0 += __shfl_xor_sync(0xffffffffu, sum0, 2);
        sum1 += __shfl_xor_sync(0xffffffffu, sum1, 1);
        sum1 += __shfl_xor_sync(0xffffffffu, sum1, 2);
        if (t4 == 0) {
            redsum[wc * 64 + R + g] = sum0;
            redsum[wc * 64 + R + g + 8] = sum1;
        }

        // ---- store P (hi/lo) for PV A-frags ----
        #pragma unroll
        for (int j = 0; j < 2; j++) {
            int kcol = wc * 16 + j * 8 + 2 * t4;
            __nv_bfloat16 h0, l0, h1, l1;
            split_bf16(s[j][0], h0, l0); split_bf16(s[j][1], h1, l1);
            *reinterpret_cast<__nv_bfloat162*>(smc + (sPh - sb) + (R + g) * PROWB + kcol * 2) =
                __nv_bfloat162(h0, h1);
            *reinterpret_cast<__nv_bfloat162*>(smc + (sPl - sb) + (R + g) * PROWB + kcol * 2) =
                __nv_bfloat162(l0, l1);
            split_bf16(s[j][2], h0, l0); split_bf16(s[j][3], h1, l1);
            *reinterpret_cast<__nv_bfloat162*>(smc + (sPh - sb) + (R + g + 8) * PROWB + kcol * 2) =
                __nv_bfloat162(h0, h1);
            *reinterpret_cast<__nv_bfloat162*>(smc + (sPl - sb) + (R + g + 8) * PROWB + kcol * 2) =
                __nv_bfloat162(l0, l1);
        }

        cp_wait1();                      // V_i ready (K_{i+1} may be pending)
        __syncthreads();                 // P + redsum visible, V ready

        l2[0] = l2[0] * a0 + sum0 + redsum[(1 - wc) * 64 + R + g];
        l2[1] = l2[1] * a1 + sum1 + redsum[(1 - wc) * 64 + R + g + 8];

        // ---- rescale O ----
        if (a0 != 1.f || a1 != 1.f) {
            #pragma unroll
            for (int i = 0; i < 16; i++) {
                o[i][0] *= a0; o[i][1] *= a0;
                o[i][2] *= a1; o[i][3] *= a1;
            }
        }

        // ---- PV: O[16 x 128] += P @ V ----
        #pragma unroll
        for (int ks = 0; ks < 2; ks++) {
            uint32_t ph[4], pl4[4];
            ldsm_x4(ph[0], ph[1], ph[2], ph[3], sPh + aoffP + ks * 32);
            ldsm_x4(pl4[0], pl4[1], pl4[2], pl4[3], sPl + aoffP + ks * 32);
            #pragma unroll
            for (int u = 0; u < 8; u++) {
                uint32_t vh[4], vl[4];
                uint32_t va = sVh + voff + ks * 16 * SROWB + u * 32;
                ldsm_x4t(vh[0], vh[1], vh[2], vh[3], va);
                ldsm_x4t(vl[0], vl[1], vl[2], vl[3], va + KPL);
                mma_bf16(o[2 * u], ph, vh);     mma_bf16(o[2 * u], ph, vl);
                mma_bf16(o[2 * u], pl4, vh);
                mma_bf16(o[2 * u + 1], ph, vh + 2); mma_bf16(o[2 * u + 1], ph, vl + 2);
                mma_bf16(o[2 * u + 1], pl4, vh + 2);
            }
        }

        __syncthreads();                 // V free
        if (has_next) issue_V(sc0 + 32);
        cp_commit();                     // pending: [K_{i+1}, V_{i+1}]
        cp_wait1();                      // K_{i+1} done before next QK^T
        __syncthreads();
    }

    // ---- epilogue: normalize, split, write enc planes ----
    float inv0 = __fdividef(1.f, l2[0]);
    float inv1 = __fdividef(1.f, l2[1]);
    #pragma unroll
    for (int nt = 0; nt < 16; nt++) {
        int dim = wc * 128 + nt * 8 + 2 * t4;
        float v0 = o[nt][0] * inv0, v1 = o[nt][1] * inv0;
        float v2 = o[nt][2] * inv1, v3 = o[nt][3] * inv1;
        __nv_bfloat16 h0, l0, h1, l1, h2, lo2, h3, l3;
        split_bf16(v0, h0, l0); split_bf16(v1, h1, l1);
        split_bf16(v2, h2, lo2); split_bf16(v3, h3, l3);
        size_t adr0 = ((size_t)tq0 * 16 + n) * 256 + dim;
        size_t adr1 = ((size_t)tq1 * 16 + n) * 256 + dim;
        *reinterpret_cast<__nv_bfloat162*>(g_ench + adr0) = __nv_bfloat162(h0, h1);
        *reinterpret_cast<__nv_bfloat162*>(g_encl + adr0) = __nv_bfloat162(l0, l1);
        *reinterpret_cast<__nv_bfloat162*>(g_ench + adr1) = __nv_bfloat162(h2, h3);
        *reinterpret_cast<__nv_bfloat162*>(g_encl + adr1) = __nv_bfloat162(lo2, l3);
    }
}

// ================= launch =================
extern "C" void kernel_launch(void* const* d_in, const int* in_sizes, int n_in,
                              void* d_out, int out_size)
{
    const float* x       = (const float*)d_in[0];
    const int*   segpos  = (const int*)  d_in[1];
    const float* w_q     = (const float*)d_in[3];
    const float* w_kv    = (const float*)d_in[4];
    const float* w_out   = (const float*)d_in[5];
    const float* q_scale = (const float*)d_in[6];
    const float* k_scale = (const float*)d_in[7];
    float*       out     = (float*)d_out;

    __nv_bfloat16 *xh, *xl, *wqh, *wql, *wkvh, *wkvl, *woh, *wol, *ench, *encl;
    float *gq, *gkv;
    cudaGetSymbolAddress((void**)&xh,   g_xh);
    cudaGetSymbolAddress((void**)&xl,   g_xl);
    cudaGetSymbolAddress((void**)&wqh,  g_wqh);
    cudaGetSymbolAddress((void**)&wql,  g_wql);
    cudaGetSymbolAddress((void**)&wkvh, g_wkvh);
    cudaGetSymbolAddress((void**)&wkvl, g_wkvl);
    cudaGetSymbolAddress((void**)&woh,  g_woh);
    cudaGetSymbolAddress((void**)&wol,  g_wol);
    cudaGetSymbolAddress((void**)&ench, g_ench);
    cudaGetSymbolAddress((void**)&encl, g_encl);
    cudaGetSymbolAddress((void**)&gq,   g_q);
    cudaGetSymbolAddress((void**)&gkv,  g_kv);

    const dim3 blk(256);

    // 0. precision prep
    convert_x_kernel<<<(T_SEQ * D_MODEL) / (256 * 4), blk>>>(x);
    transpose_conv_kernel<<<dim3(HDIM / 32, D_MODEL / 32, 16), blk>>>(w_q,  wqh, wql, D_MODEL, HDIM);
    transpose_conv_kernel<<<dim3(HDIM / 32, D_MODEL / 32, 16), blk>>>(w_kv, wkvh, wkvl, D_MODEL, HDIM);
    transpose_conv_kernel<<<dim3(D_MODEL / 32, (N_HEADS * HDIM) / 32, 1), blk>>>(
        w_out, woh, wol, N_HEADS * HDIM, D_MODEL);

    // 1. projections
    cudaFuncSetAttribute(gemm_bf16_kernel, cudaFuncAttributeMaxDynamicSharedMemorySize, GEMM_SMEM);
    gemm_bf16_kernel<<<dim3(T_SEQ / 128, HDIM / 128, 16), blk, GEMM_SMEM>>>(
        xh, xl, wqh, wql, gq, D_MODEL, (size_t)HDIM * D_MODEL, N_HEADS * HDIM, HDIM);
    gemm_bf16_kernel<<<dim3(T_SEQ / 128, HDIM / 128, 16), blk, GEMM_SMEM>>>(
        xh, xl, wkvh, wkvl, gkv, D_MODEL, (size_t)HDIM * D_MODEL, 16 * HDIM, HDIM);

    // 2. norms + rope -> bf16 hi/lo planes
    norm_rope_q_kernel <<<(T_SEQ * N_HEADS) / 8, blk>>>(q_scale, segpos);
    norm_rope_kv_kernel<<<(T_SEQ * 16) / 8,      blk>>>(k_scale, segpos);

    // 3. attention (tensor cores, v2)
    cudaFuncSetAttribute(attn_mma_kernel, cudaFuncAttributeMaxDynamicSharedMemorySize, ATTN_SMEM);
    attn_mma_kernel<<<dim3(T_SEQ / 64, N_HEADS), blk, ATTN_SMEM>>>();

    // 4. output projection
    gemm_bf16_kernel<<<dim3(T_SEQ / 128, D_MODEL / 128, 1), blk, GEMM_SMEM>>>(
        ench, encl, woh, wol, out, N_HEADS * HDIM, 0, D_MODEL, 0);
}

// round 7
// speedup vs baseline: 1.6277x; 1.0373x over previous
#include <cuda_runtime.h>
#include <cuda_bf16.h>
#include <math.h>
#include <stdint.h>

// ---------------- problem constants ----------------
#define T_SEQ   2048
#define D_MODEL 3072
#define N_HEADS 16
#define K_HEADS 8
#define HDIM    256
#define WINDOW  1024
#define SOFT_CAP 50.0f
#define EPS 1e-6f

// ---------------- scratch (static device globals) ----------------
__device__ float g_qkv[(size_t)T_SEQ * 32 * HDIM];          // [t][slot][h] slots: q0-15,k16-23,v24-31
__device__ __nv_bfloat16 g_xh [(size_t)T_SEQ * D_MODEL];
__device__ __nv_bfloat16 g_xl [(size_t)T_SEQ * D_MODEL];
__device__ __nv_bfloat16 g_qh [(size_t)T_SEQ * N_HEADS * HDIM];
__device__ __nv_bfloat16 g_ql [(size_t)T_SEQ * N_HEADS * HDIM];
__device__ __nv_bfloat16 g_kvh[(size_t)T_SEQ * 16 * HDIM];
__device__ __nv_bfloat16 g_kvl[(size_t)T_SEQ * 16 * HDIM];
__device__ __nv_bfloat16 g_wallh[(size_t)32 * HDIM * D_MODEL];  // [slot][h][d] K-major
__device__ __nv_bfloat16 g_walll[(size_t)32 * HDIM * D_MODEL];
__device__ __nv_bfloat16 g_woh [(size_t)D_MODEL * N_HEADS * HDIM];
__device__ __nv_bfloat16 g_wol [(size_t)D_MODEL * N_HEADS * HDIM];
__device__ __nv_bfloat16 g_ench[(size_t)T_SEQ * N_HEADS * HDIM];
__device__ __nv_bfloat16 g_encl[(size_t)T_SEQ * N_HEADS * HDIM];

// ---------------- low-level helpers ----------------
__device__ __forceinline__ uint32_t smem_u32(const void* p) {
    uint32_t a;
    asm("{ .reg .u64 t; cvta.to.shared.u64 t, %1; cvt.u32.u64 %0, t; }" : "=r"(a) : "l"(p));
    return a;
}
__device__ __forceinline__ void cp_async16(uint32_t dst, const void* src) {
    asm volatile("cp.async.cg.shared.global [%0], [%1], 16;" :: "r"(dst), "l"(src));
}
__device__ __forceinline__ void cp_commit() { asm volatile("cp.async.commit_group;"); }
__device__ __forceinline__ void cp_wait1()  { asm volatile("cp.async.wait_group 1;"); }

__device__ __forceinline__ void ldsm_x4(uint32_t& r0, uint32_t& r1, uint32_t& r2, uint32_t& r3,
                                        uint32_t addr) {
    asm volatile("ldmatrix.sync.aligned.m8n8.x4.shared.b16 {%0,%1,%2,%3}, [%4];"
                 : "=r"(r0), "=r"(r1), "=r"(r2), "=r"(r3) : "r"(addr));
}
__device__ __forceinline__ void ldsm_x4t(uint32_t& r0, uint32_t& r1, uint32_t& r2, uint32_t& r3,
                                         uint32_t addr) {
    asm volatile("ldmatrix.sync.aligned.m8n8.x4.trans.shared.b16 {%0,%1,%2,%3}, [%4];"
                 : "=r"(r0), "=r"(r1), "=r"(r2), "=r"(r3) : "r"(addr));
}
__device__ __forceinline__ void mma_bf16(float* c, const uint32_t* a, const uint32_t* b) {
    asm volatile("mma.sync.aligned.m16n8k16.row.col.f32.bf16.bf16.f32 "
                 "{%0,%1,%2,%3},{%4,%5,%6,%7},{%8,%9},{%0,%1,%2,%3};"
                 : "+f"(c[0]), "+f"(c[1]), "+f"(c[2]), "+f"(c[3])
                 : "r"(a[0]), "r"(a[1]), "r"(a[2]), "r"(a[3]), "r"(b[0]), "r"(b[1]));
}
__device__ __forceinline__ void split_bf16(float x, __nv_bfloat16& h, __nv_bfloat16& l) {
    h = __float2bfloat16(x);
    l = __float2bfloat16(x - __bfloat162float(h));
}

// ================= split-bf16 GEMM, templated M-tile =================
// MT=128: 8 warps 2Mx4N (warp 64x32).  MT=64: 8 warps 1Mx8N (warp 64x16).
// A planes [M][K]; B planes [z][N][K] K-major; C fp32, col = z*czcol + n0.
#define LDHB 80                       // smem row bytes (40 halves)
template<int MT>
__global__ __launch_bounds__(256) void gemm_bf16_kernel(
    const __nv_bfloat16* __restrict__ Ah, const __nv_bfloat16* __restrict__ Al,
    const __nv_bfloat16* __restrict__ Bh, const __nv_bfloat16* __restrict__ Bl,
    float* __restrict__ C, int Kdim, size_t b_zstride, int ldc, int czcol)
{
    constexpr int APL = MT * LDHB;          // A plane bytes
    constexpr int BPL = 128 * LDHB;         // B plane bytes
    constexpr int STAGE = 2 * APL + 2 * BPL;
    constexpr int NST = 3;
    constexpr int JW = (MT == 128) ? 4 : 2; // j frags per warp
    constexpr int WNW = (MT == 128) ? 32 : 16;

    extern __shared__ char smem[];
    const uint32_t sbase = smem_u32(smem);
    const int tid = threadIdx.x;
    const int m0 = blockIdx.x * MT, n0b = blockIdx.y * 128, z = blockIdx.z;
    const __nv_bfloat16* Ahm = Ah + (size_t)m0 * Kdim;
    const __nv_bfloat16* Alm = Al + (size_t)m0 * Kdim;
    const __nv_bfloat16* Bhz = Bh + (size_t)z * b_zstride + (size_t)n0b * Kdim;
    const __nv_bfloat16* Blz = Bl + (size_t)z * b_zstride + (size_t)n0b * Kdim;
    const int ccol = z * czcol + n0b;
    const int NK = Kdim / 32;

    const int wid = tid >> 5, lane = tid & 31;
    const int wm = (MT == 128) ? (wid & 1) : 0;
    const int wn = (MT == 128) ? (wid >> 1) : wid;
    const int g = lane >> 2, t4 = lane & 3;

    auto issue_stage = [&](int s, int kt) {
        const int k0 = kt * 32;
        const uint32_t stg = sbase + s * STAGE;
        #pragma unroll
        for (int i = 0; i < MT * 4 / 256; i++) {
            int idx = tid + i * 256;
            int r = idx >> 2, c = idx & 3;
            size_t goff = (size_t)r * Kdim + k0 + c * 8;
            uint32_t d = stg + r * LDHB + c * 16;
            cp_async16(d,       Ahm + goff);
            cp_async16(d + APL, Alm + goff);
        }
        #pragma unroll
        for (int i = 0; i < 2; i++) {
            int idx = tid + i * 256;
            int r = idx >> 2, c = idx & 3;
            size_t goff = (size_t)r * Kdim + k0 + c * 8;
            uint32_t d = stg + 2 * APL + r * LDHB + c * 16;
            cp_async16(d,       Bhz + goff);
            cp_async16(d + BPL, Blz + goff);
        }
    };

    float acc[4][JW][4];
    #pragma unroll
    for (int i = 0; i < 4; i++)
        #pragma unroll
        for (int j = 0; j < JW; j++)
            #pragma unroll
            for (int r = 0; r < 4; r++) acc[i][j][r] = 0.f;

    const int arow = wm * 64 + (lane & 7) + ((lane >> 3) & 1) * 8;
    const int akof = ((lane >> 4) & 1) * 8;
    const int brow = wn * WNW + (lane & 7) + ((lane >> 4) & 1) * 8;
    const int bkof = ((lane >> 3) & 1) * 8;

    issue_stage(0, 0); cp_commit();
    issue_stage(1, 1); cp_commit();

    for (int kt = 0; kt < NK; kt++) {
        cp_wait1();
        __syncthreads();
        if (kt + 2 < NK) issue_stage((kt + 2) % NST, kt + 2);
        cp_commit();

        const uint32_t st = sbase + (kt % NST) * STAGE;
        #pragma unroll
        for (int ks = 0; ks < 2; ks++) {
            uint32_t ah[4][4], al[4][4], bh[JW][2], bl[JW][2];
            #pragma unroll
            for (int i = 0; i < 4; i++) {
                uint32_t ad = st + (arow + i * 16) * LDHB + (ks * 16 + akof) * 2;
                ldsm_x4(ah[i][0], ah[i][1], ah[i][2], ah[i][3], ad);
                ldsm_x4(al[i][0], al[i][1], al[i][2], al[i][3], ad + APL);
            }
            #pragma unroll
            for (int jp = 0; jp < JW / 2; jp++) {
                uint32_t bd = st + 2 * APL + (brow + jp * 16) * LDHB + (ks * 16 + bkof) * 2;
                uint32_t r0, r1, r2, r3;
                ldsm_x4(r0, r1, r2, r3, bd);
                bh[2 * jp][0] = r0; bh[2 * jp][1] = r1;
                bh[2 * jp + 1][0] = r2; bh[2 * jp + 1][1] = r3;
                ldsm_x4(r0, r1, r2, r3, bd + BPL);
                bl[2 * jp][0] = r0; bl[2 * jp][1] = r1;
                bl[2 * jp + 1][0] = r2; bl[2 * jp + 1][1] = r3;
            }
            #pragma unroll
            for (int i = 0; i < 4; i++)
                #pragma unroll
                for (int j = 0; j < JW; j++) {
                    mma_bf16(acc[i][j], ah[i], bh[j]);
                    mma_bf16(acc[i][j], ah[i], bl[j]);
                    mma_bf16(acc[i][j], al[i], bh[j]);
                }
        }
    }

    #pragma unroll
    for (int i = 0; i < 4; i++) {
        const int r0 = m0 + wm * 64 + i * 16 + g;
        #pragma unroll
        for (int j = 0; j < JW; j++) {
            const int c0 = ccol + wn * WNW + j * 8 + t4 * 2;
            *reinterpret_cast<float2*>(&C[(size_t)r0 * ldc + c0]) =
                make_float2(acc[i][j][0], acc[i][j][1]);
            *reinterpret_cast<float2*>(&C[(size_t)(r0 + 8) * ldc + c0]) =
                make_float2(acc[i][j][2], acc[i][j][3]);
        }
    }
}

#define GEMM_SMEM_128 (3 * (2 * 128 * LDHB + 2 * 128 * LDHB))   // 122880
#define GEMM_SMEM_64  (3 * (2 * 64 * LDHB + 2 * 128 * LDHB))    // 92160

// ================= x -> bf16 hi/lo planes =================
__global__ __launch_bounds__(256) void convert_x_kernel(const float* __restrict__ x)
{
    size_t i = ((size_t)blockIdx.x * 256 + threadIdx.x) * 4;
    float4 v = *reinterpret_cast<const float4*>(x + i);
    __nv_bfloat16 h[4], l[4];
    split_bf16(v.x, h[0], l[0]); split_bf16(v.y, h[1], l[1]);
    split_bf16(v.z, h[2], l[2]); split_bf16(v.w, h[3], l[3]);
    *reinterpret_cast<__nv_bfloat162*>(g_xh + i)     = __nv_bfloat162(h[0], h[1]);
    *reinterpret_cast<__nv_bfloat162*>(g_xh + i + 2) = __nv_bfloat162(h[2], h[3]);
    *reinterpret_cast<__nv_bfloat162*>(g_xl + i)     = __nv_bfloat162(l[0], l[1]);
    *reinterpret_cast<__nv_bfloat162*>(g_xl + i + 2) = __nv_bfloat162(l[2], l[3]);
}

// ================= transpose + convert: [z][R][C] fp32 -> [z][C][R] bf16 hi/lo =================
__global__ __launch_bounds__(256) void transpose_conv_kernel(
    const float* __restrict__ in, __nv_bfloat16* __restrict__ outh,
    __nv_bfloat16* __restrict__ outl, int R, int C)
{
    __shared__ float t[32][33];
    size_t zo = (size_t)blockIdx.z * R * C;
    int c0 = blockIdx.x * 32, r0 = blockIdx.y * 32;
    int tx = threadIdx.x & 31, ty = threadIdx.x >> 5;
    #pragma unroll
    for (int i = 0; i < 32; i += 8)
        t[ty + i][tx] = in[zo + (size_t)(r0 + ty + i) * C + c0 + tx];
    __syncthreads();
    #pragma unroll
    for (int i = 0; i < 32; i += 8) {
        float v = t[tx][ty + i];
        __nv_bfloat16 h, l;
        split_bf16(v, h, l);
        size_t o = zo + (size_t)(c0 + ty + i) * R + r0 + tx;
        outh[o] = h;
        outl[o] = l;
    }
}

// ================= RMS-norm (+scale) (+RoPE) -> bf16 hi/lo planes =================
__device__ __forceinline__ void rope_apply(float v[8], int lane, int pos)
{
    #pragma unroll
    for (int j = 0; j < 4; j++) {
        int hh = lane + 32 * j;
        float ts = powf(10000.0f, (float)hh * (1.0f / 128.0f));
        float arg = (float)pos / ts;
        float sn, cs;
        sincosf(arg, &sn, &cs);
        float f = v[j], s = v[j + 4];
        v[j]     = f * cs - s * sn;
        v[j + 4] = s * cs + f * sn;
    }
}

__global__ __launch_bounds__(256) void norm_rope_q_kernel(const float* __restrict__ qscale,
                                                          const int* __restrict__ segpos)
{
    int row  = blockIdx.x * 8 + (threadIdx.x >> 5);   // 0..T*16-1
    int lane = threadIdx.x & 31;
    int t = row >> 4, head = row & 15;
    const float* p = g_qkv + ((size_t)t * 32 + head) * HDIM;

    float v[8]; float ss = 0.f;
    #pragma unroll
    for (int j = 0; j < 8; j++) { v[j] = p[lane + 32 * j]; ss += v[j] * v[j]; }
    #pragma unroll
    for (int o = 16; o > 0; o >>= 1) ss += __shfl_xor_sync(0xffffffffu, ss, o);
    float rstd = rsqrtf(ss * (1.0f / 256.0f) + EPS);

    #pragma unroll
    for (int j = 0; j < 8; j++) {
        int h = lane + 32 * j;
        v[j] = v[j] * rstd * (1.0f + qscale[h]);
    }
    rope_apply(v, lane, segpos[t]);
    #pragma unroll
    for (int j = 0; j < 8; j++) {
        int h = lane + 32 * j;
        __nv_bfloat16 hh, ll;
        split_bf16(v[j], hh, ll);
        g_qh[(size_t)row * HDIM + h] = hh;
        g_ql[(size_t)row * HDIM + h] = ll;
    }
}

__global__ __launch_bounds__(256) void norm_rope_kv_kernel(const float* __restrict__ kscale,
                                                           const int* __restrict__ segpos)
{
    int row  = blockIdx.x * 8 + (threadIdx.x >> 5);   // 0..T*16-1 (8 K + 8 V per t)
    int lane = threadIdx.x & 31;
    int t    = row >> 4;
    int head = row & 15;                              // <8 K, >=8 V
    const float* p = g_qkv + ((size_t)t * 32 + 16 + head) * HDIM;

    float v[8]; float ss = 0.f;
    #pragma unroll
    for (int j = 0; j < 8; j++) { v[j] = p[lane + 32 * j]; ss += v[j] * v[j]; }
    #pragma unroll
    for (int o = 16; o > 0; o >>= 1) ss += __shfl_xor_sync(0xffffffffu, ss, o);
    float rstd = rsqrtf(ss * (1.0f / 256.0f) + EPS);

    if (head < 8) {
        #pragma unroll
        for (int j = 0; j < 8; j++) {
            int h = lane + 32 * j;
            v[j] = v[j] * rstd * (1.0f + kscale[h]);
        }
        rope_apply(v, lane, segpos[t]);
    } else {
        #pragma unroll
        for (int j = 0; j < 8; j++) v[j] *= rstd;
    }
    #pragma unroll
    for (int j = 0; j < 8; j++) {
        int h = lane + 32 * j;
        __nv_bfloat16 hh, ll;
        split_bf16(v[j], hh, ll);
        g_kvh[(size_t)row * HDIM + h] = hh;
        g_kvl[(size_t)row * HDIM + h] = ll;
    }
}

// ================= tensor-core flash attention (unchanged from R6 winner) =================
#define SROWB 528
#define QPL 33792
#define KPL 16896
#define PROWB 80
#define PPL (64 * PROWB)
#define ATTN_SMEM (2 * QPL + 4 * KPL + 2 * PPL + 1024)

__global__ __launch_bounds__(256, 1) void attn_mma_kernel()
{
    extern __shared__ char smc[];
    const uint32_t sb = smem_u32(smc);
    const int tid = threadIdx.x;
    const int wid = tid >> 5, lane = tid & 31;
    const int t0 = blockIdx.x * 64;
    const int n  = blockIdx.y;
    const int hp = n >> 1;
    const int wr = wid & 3, wc = wid >> 2;
    const int R  = wr * 16;
    const int g = lane >> 2, t4 = lane & 3;

    const uint32_t sQh = sb, sQl = sb + QPL;
    const uint32_t sKh = sb + 2 * QPL;
    const uint32_t sKl = sKh + KPL;
    const uint32_t sVh = sKh + 2 * KPL;
    const uint32_t sVl = sKh + 3 * KPL;
    const uint32_t sPh = sb + 2 * QPL + 4 * KPL;
    const uint32_t sPl = sPh + PPL;
    float* redmax = reinterpret_cast<float*>(smc + 2 * QPL + 4 * KPL + 2 * PPL);
    float* redsum = redmax + 128;

    #pragma unroll
    for (int i = 0; i < 16; i++) {
        int idx = tid + i * 256;
        int pl = idx >> 11;
        int r = (idx >> 5) & 63, c = idx & 31;
        const __nv_bfloat16* src = (pl ? g_ql : g_qh) +
            ((size_t)(t0 + r) * 16 + n) * 256 + c * 8;
        cp_async16(sb + pl * QPL + r * SROWB + c * 16, src);
    }
    cp_commit();

    auto issue_K = [&](int sc0) {
        #pragma unroll
        for (int i = 0; i < 8; i++) {
            int idx = tid + i * 256;
            int pl = idx >> 10;
            int r = (idx >> 5) & 31, c = idx & 31;
            const __nv_bfloat16* src = (pl ? g_kvl : g_kvh) +
                ((size_t)(sc0 + r) * 16 + hp) * 256 + c * 8;
            cp_async16(sKh + pl * KPL + r * SROWB + c * 16, src);
        }
    };
    auto issue_V = [&](int sc0) {
        #pragma unroll
        for (int i = 0; i < 8; i++) {
            int idx = tid + i * 256;
            int pl = idx >> 10;
            int r = (idx >> 5) & 31, c = idx & 31;
            const __nv_bfloat16* src = (pl ? g_kvl : g_kvh) +
                ((size_t)(sc0 + r) * 16 + 8 + hp) * 256 + c * 8;
            cp_async16(sVh + pl * KPL + r * SROWB + c * 16, src);
        }
    };

    float o[16][4];
    #pragma unroll
    for (int i = 0; i < 16; i++)
        #pragma unroll
        for (int c = 0; c < 4; c++) o[i][c] = 0.f;
    float m2[2] = {-1e29f, -1e29f}, l2[2] = {0.f, 0.f};

    int s_lo = t0 - (WINDOW - 1); if (s_lo < 0) s_lo = 0; s_lo &= ~31;

    const int aoff  = (R + (lane & 7) + ((lane >> 3) & 1) * 8) * SROWB + ((lane >> 4) & 1) * 16;
    const int koff  = (((lane >> 4) & 1) * 8 + (lane & 7)) * SROWB + ((lane >> 3) & 1) * 16
                      + wc * 16 * SROWB;
    const int voff  = (((lane >> 3) & 1) * 8 + (lane & 7)) * SROWB + ((lane >> 4) & 1) * 16
                      + wc * 256;
    const int aoffP = (R + (lane & 7) + ((lane >> 3) & 1) * 8) * PROWB + ((lane >> 4) & 1) * 16;
    const int tq0 = t0 + R + g, tq1 = tq0 + 8;

    issue_K(s_lo); cp_commit();
    issue_V(s_lo); cp_commit();
    asm volatile("cp.async.wait_group 1;");
    __syncthreads();

    for (int sc0 = s_lo; sc0 <= t0 + 63; sc0 += 32) {
        const bool has_next = (sc0 + 32 <= t0 + 63);

        float s[2][4];
        #pragma unroll
        for (int j = 0; j < 2; j++)
            #pragma unroll
            for (int c = 0; c < 4; c++) s[j][c] = 0.f;

        #pragma unroll 4
        for (int hs = 0; hs < 16; hs++) {
            uint32_t qh[4], ql[4], kh[4], kl[4];
            ldsm_x4(qh[0], qh[1], qh[2], qh[3], sQh + aoff + hs * 32);
            ldsm_x4(ql[0], ql[1], ql[2], ql[3], sQl + aoff + hs * 32);
            ldsm_x4(kh[0], kh[1], kh[2], kh[3], sKh + koff + hs * 32);
            ldsm_x4(kl[0], kl[1], kl[2], kl[3], sKl + koff + hs * 32);
            mma_bf16(s[0], qh, kh); mma_bf16(s[0], qh, kl); mma_bf16(s[0], ql, kh);
            mma_bf16(s[1], qh, kh + 2); mma_bf16(s[1], qh, kl + 2); mma_bf16(s[1], ql, kh + 2);
        }

        #pragma unroll
        for (int j = 0; j < 2; j++)
            #pragma unroll
            for (int c = 0; c < 4; c++) {
                int tq = (c >> 1) ? tq1 : tq0;
                int sk = sc0 + wc * 16 + j * 8 + 2 * t4 + (c & 1);
                float xx = s[j][c] * (1.0f / SOFT_CAP);
                xx = fminf(fmaxf(xx, -10.f), 10.f);
                float e = __expf(2.0f * xx);
                float val = SOFT_CAP * __fdividef(e - 1.0f, e + 1.0f);
                bool ok = (sk <= tq) && (sk > tq - WINDOW);
                s[j][c] = ok ? val : -1e30f;
            }

        float mx0 = fmaxf(fmaxf(s[0][0], s[0][1]), fmaxf(s[1][0], s[1][1]));
        float mx1 = fmaxf(fmaxf(s[0][2], s[0][3]), fmaxf(s[1][2], s[1][3]));
        mx0 = fmaxf(mx0, __shfl_xor_sync(0xffffffffu, mx0, 1));
        mx0 = fmaxf(mx0, __shfl_xor_sync(0xffffffffu, mx0, 2));
        mx1 = fmaxf(mx1, __shfl_xor_sync(0xffffffffu, mx1, 1));
        mx1 = fmaxf(mx1, __shfl_xor_sync(0xffffffffu, mx1, 2));
        if (t4 == 0) {
            redmax[wc * 64 + R + g] = mx0;
            redmax[wc * 64 + R + g + 8] = mx1;
        }
        __syncthreads();

        if (has_next) issue_K(sc0 + 32);
        cp_commit();

        float cm0 = fmaxf(mx0, redmax[(1 - wc) * 64 + R + g]);
        float cm1 = fmaxf(mx1, redmax[(1 - wc) * 64 + R + g + 8]);
        float mn0 = fmaxf(m2[0], cm0), mn1 = fmaxf(m2[1], cm1);
        float a0 = __expf(m2[0] - mn0), a1 = __expf(m2[1] - mn1);
        m2[0] = mn0; m2[1] = mn1;

        float sum0 = 0.f, sum1 = 0.f;
        #pragma unroll
        for (int j = 0; j < 2; j++) {
            s[j][0] = __expf(s[j][0] - mn0); sum0 += s[j][0];
            s[j][1] = __expf(s[j][1] - mn0); sum0 += s[j][1];
            s[j][2] = __expf(s[j][2] - mn1); sum1 += s[j][2];
            s[j][3] = __expf(s[j][3] - mn1); sum1 += s[j][3];
        }
        sum0 += __shfl_xor_sync(0xffffffffu, sum0, 1);
        sum0 += __shfl_xor_sync(0xffffffffu, sum0, 2);
        sum1 += __shfl_xor_sync(0xffffffffu, sum1, 1);
        sum1 += __shfl_xor_sync(0xffffffffu, sum1, 2);
        if (t4 == 0) {
            redsum[wc * 64 + R + g] = sum0;
            redsum[wc * 64 + R + g + 8] = sum1;
        }

        #pragma unroll
        for (int j = 0; j < 2; j++) {
            int kcol = wc * 16 + j * 8 + 2 * t4;
            __nv_bfloat16 h0, l0, h1, l1;
            split_bf16(s[j][0], h0, l0); split_bf16(s[j][1], h1, l1);
            *reinterpret_cast<__nv_bfloat162*>(smc + (sPh - sb) + (R + g) * PROWB + kcol * 2) =
                __nv_bfloat162(h0, h1);
            *reinterpret_cast<__nv_bfloat162*>(smc + (sPl - sb) + (R + g) * PROWB + kcol * 2) =
                __nv_bfloat162(l0, l1);
            split_bf16(s[j][2], h0, l0); split_bf16(s[j][3], h1, l1);
            *reinterpret_cast<__nv_bfloat162*>(smc + (sPh - sb) + (R + g + 8) * PROWB + kcol * 2) =
                __nv_bfloat162(h0, h1);
            *reinterpret_cast<__nv_bfloat162*>(smc + (sPl - sb) + (R + g + 8) * PROWB + kcol * 2) =
                __nv_bfloat162(l0, l1);
        }

        cp_wait1();
        __syncthreads();

        l2[0] = l2[0] * a0 + sum0 + redsum[(1 - wc) * 64 + R + g];
        l2[1] = l2[1] * a1 + sum1 + redsum[(1 - wc) * 64 + R + g + 8];

        if (a0 != 1.f || a1 != 1.f) {
            #pragma unroll
            for (int i = 0; i < 16; i++) {
                o[i][0] *= a0; o[i][1] *= a0;
                o[i][2] *= a1; o[i][3] *= a1;
            }
        }

        #pragma unroll
        for (int ks = 0; ks < 2; ks++) {
            uint32_t ph[4], pl4[4];
            ldsm_x4(ph[0], ph[1], ph[2], ph[3], sPh + aoffP + ks * 32);
            ldsm_x4(pl4[0], pl4[1], pl4[2], pl4[3], sPl + aoffP + ks * 32);
            #pragma unroll
            for (int u = 0; u < 8; u++) {
                uint32_t vh[4], vl[4];
                uint32_t va = sVh + voff + ks * 16 * SROWB + u * 32;
                ldsm_x4t(vh[0], vh[1], vh[2], vh[3], va);
                ldsm_x4t(vl[0], vl[1], vl[2], vl[3], va + KPL);
                mma_bf16(o[2 * u], ph, vh);     mma_bf16(o[2 * u], ph, vl);
                mma_bf16(o[2 * u], pl4, vh);
                mma_bf16(o[2 * u + 1], ph, vh + 2); mma_bf16(o[2 * u + 1], ph, vl + 2);
                mma_bf16(o[2 * u + 1], pl4, vh + 2);
            }
        }

        __syncthreads();
        if (has_next) issue_V(sc0 + 32);
        cp_commit();
        cp_wait1();
        __syncthreads();
    }

    float inv0 = __fdividef(1.f, l2[0]);
    float inv1 = __fdividef(1.f, l2[1]);
    #pragma unroll
    for (int nt = 0; nt < 16; nt++) {
        int dim = wc * 128 + nt * 8 + 2 * t4;
        float v0 = o[nt][0] * inv0, v1 = o[nt][1] * inv0;
        float v2 = o[nt][2] * inv1, v3 = o[nt][3] * inv1;
        __nv_bfloat16 h0, l0, h1, l1, h2, lo2, h3, l3;
        split_bf16(v0, h0, l0); split_bf16(v1, h1, l1);
        split_bf16(v2, h2, lo2); split_bf16(v3, h3, l3);
        size_t adr0 = ((size_t)tq0 * 16 + n) * 256 + dim;
        size_t adr1 = ((size_t)tq1 * 16 + n) * 256 + dim;
        *reinterpret_cast<__nv_bfloat162*>(g_ench + adr0) = __nv_bfloat162(h0, h1);
        *reinterpret_cast<__nv_bfloat162*>(g_encl + adr0) = __nv_bfloat162(l0, l1);
        *reinterpret_cast<__nv_bfloat162*>(g_ench + adr1) = __nv_bfloat162(h2, h3);
        *reinterpret_cast<__nv_bfloat162*>(g_encl + adr1) = __nv_bfloat162(lo2, l3);
    }
}

// ================= launch =================
extern "C" void kernel_launch(void* const* d_in, const int* in_sizes, int n_in,
                              void* d_out, int out_size)
{
    const float* x       = (const float*)d_in[0];
    const int*   segpos  = (const int*)  d_in[1];
    const float* w_q     = (const float*)d_in[3];
    const float* w_kv    = (const float*)d_in[4];
    const float* w_out   = (const float*)d_in[5];
    const float* q_scale = (const float*)d_in[6];
    const float* k_scale = (const float*)d_in[7];
    float*       out     = (float*)d_out;

    __nv_bfloat16 *xh, *xl, *wallh, *walll, *woh, *wol, *ench, *encl;
    float *gqkv;
    cudaGetSymbolAddress((void**)&xh,    g_xh);
    cudaGetSymbolAddress((void**)&xl,    g_xl);
    cudaGetSymbolAddress((void**)&wallh, g_wallh);
    cudaGetSymbolAddress((void**)&walll, g_walll);
    cudaGetSymbolAddress((void**)&woh,   g_woh);
    cudaGetSymbolAddress((void**)&wol,   g_wol);
    cudaGetSymbolAddress((void**)&ench,  g_ench);
    cudaGetSymbolAddress((void**)&encl,  g_encl);
    cudaGetSymbolAddress((void**)&gqkv,  g_qkv);

    const dim3 blk(256);
    const size_t hslot = (size_t)HDIM * D_MODEL;   // per-slot plane size

    // 0. precision prep: x planes; weights -> merged K-major plane buffer
    convert_x_kernel<<<(T_SEQ * D_MODEL) / (256 * 4), blk>>>(x);
    transpose_conv_kernel<<<dim3(HDIM / 32, D_MODEL / 32, 16), blk>>>(
        w_q, wallh, walll, D_MODEL, HDIM);                         // slots 0..15
    transpose_conv_kernel<<<dim3(HDIM / 32, D_MODEL / 32, 16), blk>>>(
        w_kv, wallh + 16 * hslot, walll + 16 * hslot, D_MODEL, HDIM); // slots 16..31
    transpose_conv_kernel<<<dim3(D_MODEL / 32, (N_HEADS * HDIM) / 32, 1), blk>>>(
        w_out, woh, wol, N_HEADS * HDIM, D_MODEL);

    // 1. merged Q+K+V projection: one launch, 1024 CTAs
    cudaFuncSetAttribute(gemm_bf16_kernel<128>, cudaFuncAttributeMaxDynamicSharedMemorySize, GEMM_SMEM_128);
    cudaFuncSetAttribute(gemm_bf16_kernel<64>,  cudaFuncAttributeMaxDynamicSharedMemorySize, GEMM_SMEM_64);
    gemm_bf16_kernel<128><<<dim3(T_SEQ / 128, HDIM / 128, 32), blk, GEMM_SMEM_128>>>(
        xh, xl, wallh, walll, gqkv, D_MODEL, hslot, 32 * HDIM, HDIM);

    // 2. norms + rope -> bf16 hi/lo planes
    norm_rope_q_kernel <<<(T_SEQ * N_HEADS) / 8, blk>>>(q_scale, segpos);
    norm_rope_kv_kernel<<<(T_SEQ * 16) / 8,      blk>>>(k_scale, segpos);

    // 3. attention (tensor cores)
    cudaFuncSetAttribute(attn_mma_kernel, cudaFuncAttributeMaxDynamicSharedMemorySize, ATTN_SMEM);
    attn_mma_kernel<<<dim3(T_SEQ / 64, N_HEADS), blk, ATTN_SMEM>>>();

    // 4. output projection: M-tile 64 -> 768 CTAs, no wave tail
    gemm_bf16_kernel<64><<<dim3(T_SEQ / 64, D_MODEL / 128, 1), blk, GEMM_SMEM_64>>>(
        ench, encl, woh, wol, out, N_HEADS * HDIM, 0, D_MODEL, 0);
}